// round 1
// baseline (speedup 1.0000x reference)
#include <cuda_runtime.h>
#include <cuda_bf16.h>
#include <math.h>

#define N_NODES 20000
#define N_EDGES 640000

// ---------------- device scratch (no allocation allowed) ----------------
static __device__ float g_ycat1[N_NODES * 128]; // [y1 (64) | r1 (64)]
static __device__ float g_h1[N_NODES * 64];
static __device__ float g_h[N_NODES * 32];
static __device__ float g_ycat2[N_NODES * 32];  // [y2 (16) | r2 (16)]
static __device__ float g_h2[N_NODES * 16];

static __device__ int g_deg[N_NODES];
static __device__ int g_off[N_NODES + 1];
static __device__ int g_cur[N_NODES];
static __device__ int g_csr_src[N_EDGES];
static __device__ int g_is64;

// ---------------- edge-index dtype handling ----------------
__global__ void detect_kernel(const long long* __restrict__ e) {
    long long v = e[threadIdx.x];
    bool ok = (v >= 0 && v < (long long)N_NODES);
    unsigned m = __ballot_sync(0xffffffffu, ok);
    if (threadIdx.x == 0) g_is64 = (m == 0xffffffffu) ? 1 : 0;
}

__device__ __forceinline__ int load_idx(const void* e, int i, int is64) {
    if (is64) return (int)((const long long*)e)[i];
    return ((const int*)e)[i];
}

// ---------------- CSR build ----------------
__global__ void zero_deg_kernel() {
    int i = blockIdx.x * blockDim.x + threadIdx.x;
    if (i < N_NODES) g_deg[i] = 0;
}

__global__ void hist_kernel(const void* __restrict__ e) {
    int i = blockIdx.x * blockDim.x + threadIdx.x;
    if (i >= N_EDGES) return;
    int is64 = g_is64;
    int dst = load_idx(e, N_EDGES + i, is64);
    atomicAdd(&g_deg[dst], 1);
}

__global__ void scan_kernel() {
    __shared__ int s[1024];
    const int CH = (N_NODES + 1023) / 1024; // 20
    int tid = threadIdx.x;
    int base = tid * CH;
    int sum = 0;
    for (int i = 0; i < CH; i++) {
        int idx = base + i;
        if (idx < N_NODES) sum += g_deg[idx];
    }
    s[tid] = sum;
    __syncthreads();
    // Kogge-Stone inclusive scan
    for (int d = 1; d < 1024; d <<= 1) {
        int v = (tid >= d) ? s[tid - d] : 0;
        __syncthreads();
        s[tid] += v;
        __syncthreads();
    }
    int run = (tid == 0) ? 0 : s[tid - 1];
    for (int i = 0; i < CH; i++) {
        int idx = base + i;
        if (idx < N_NODES) {
            g_off[idx] = run;
            g_cur[idx] = run;
            run += g_deg[idx];
        }
    }
    if (tid == 1023) g_off[N_NODES] = s[1023];
}

__global__ void fill_kernel(const void* __restrict__ e) {
    int i = blockIdx.x * blockDim.x + threadIdx.x;
    if (i >= N_EDGES) return;
    int is64 = g_is64;
    int src = load_idx(e, i, is64);
    int dst = load_idx(e, N_EDGES + i, is64);
    int pos = atomicAdd(&g_cur[dst], 1);
    g_csr_src[pos] = src;
}

// ---------------- GEMM 1: x[20000,128] -> ycat1[20000,128] = [x@w_rel1 | x@w_root1]
__global__ void proj1_kernel(const float* __restrict__ x,
                             const float* __restrict__ w_rel,
                             const float* __restrict__ w_root) {
    __shared__ float xs[64][33];
    __shared__ float ws[32][128];
    int tid = threadIdx.x;
    int c = tid & 31;   // column group base
    int r = tid >> 5;   // row base 0..7
    int node0 = blockIdx.x * 64;
    float acc[8][4];
#pragma unroll
    for (int m = 0; m < 8; m++)
#pragma unroll
        for (int g = 0; g < 4; g++) acc[m][g] = 0.f;

    for (int kc = 0; kc < 128; kc += 32) {
        for (int t = tid; t < 64 * 32; t += 256) {
            int nn = t >> 5, kk = t & 31;
            int gn = node0 + nn;
            xs[nn][kk] = (gn < N_NODES) ? x[gn * 128 + kc + kk] : 0.f;
        }
        for (int t = tid; t < 32 * 128; t += 256) {
            int kk = t >> 7, j = t & 127;
            float v = (j < 64) ? w_rel[(kc + kk) * 64 + j]
                               : w_root[(kc + kk) * 64 + (j - 64)];
            ws[kk][j] = v;
        }
        __syncthreads();
#pragma unroll
        for (int kk = 0; kk < 32; kk++) {
            float wv[4];
#pragma unroll
            for (int g = 0; g < 4; g++) wv[g] = ws[kk][c + 32 * g];
#pragma unroll
            for (int m = 0; m < 8; m++) {
                float xv = xs[r + 8 * m][kk];
#pragma unroll
                for (int g = 0; g < 4; g++) acc[m][g] += xv * wv[g];
            }
        }
        __syncthreads();
    }
#pragma unroll
    for (int m = 0; m < 8; m++) {
        int gn = node0 + r + 8 * m;
        if (gn < N_NODES) {
#pragma unroll
            for (int g = 0; g < 4; g++)
                g_ycat1[gn * 128 + c + 32 * g] = acc[m][g];
        }
    }
}

// ---------------- agg1: h1 = segsum(y1) + r1 + b_rel1   (warp per node, 64 feats)
__global__ void agg1_kernel(const float* __restrict__ b_rel) {
    int warp = (blockIdx.x * blockDim.x + threadIdx.x) >> 5;
    int lane = threadIdx.x & 31;
    if (warp >= N_NODES) return;
    int node = warp;
    int beg = g_off[node], end = g_off[node + 1];
    float a0 = 0.f, a1 = 0.f;
    int e = beg;
    for (; e + 4 <= end; e += 4) {
        int s0 = g_csr_src[e];
        int s1 = g_csr_src[e + 1];
        int s2 = g_csr_src[e + 2];
        int s3 = g_csr_src[e + 3];
        float v00 = g_ycat1[s0 * 128 + lane],      v01 = g_ycat1[s0 * 128 + 32 + lane];
        float v10 = g_ycat1[s1 * 128 + lane],      v11 = g_ycat1[s1 * 128 + 32 + lane];
        float v20 = g_ycat1[s2 * 128 + lane],      v21 = g_ycat1[s2 * 128 + 32 + lane];
        float v30 = g_ycat1[s3 * 128 + lane],      v31 = g_ycat1[s3 * 128 + 32 + lane];
        a0 += v00 + v10 + v20 + v30;
        a1 += v01 + v11 + v21 + v31;
    }
    for (; e < end; e++) {
        int s = g_csr_src[e];
        a0 += g_ycat1[s * 128 + lane];
        a1 += g_ycat1[s * 128 + 32 + lane];
    }
    float h0 = a0 + g_ycat1[node * 128 + 64 + lane] + b_rel[lane];
    float h1v = a1 + g_ycat1[node * 128 + 96 + lane] + b_rel[lane + 32];
    g_h1[node * 64 + lane] = h0;
    g_h1[node * 64 + 32 + lane] = h1v;
}

// ---------------- GEMM 2: h = relu(h1 @ w_l1 + b_l1)   [20000,64]->[20000,32]
__global__ void mlp1_kernel(const float* __restrict__ w_l1,
                            const float* __restrict__ b_l1) {
    __shared__ float xs[64][65];
    __shared__ float ws[64][32];
    __shared__ float bs[32];
    int tid = threadIdx.x;
    int c = tid & 31;
    int r = tid >> 5;
    int node0 = blockIdx.x * 64;
    for (int t = tid; t < 64 * 64; t += 256) {
        int nn = t >> 6, kk = t & 63;
        int gn = node0 + nn;
        xs[nn][kk] = (gn < N_NODES) ? g_h1[gn * 64 + kk] : 0.f;
    }
    for (int t = tid; t < 64 * 32; t += 256) {
        int kk = t >> 5, j = t & 31;
        ws[kk][j] = w_l1[kk * 32 + j];
    }
    if (tid < 32) bs[tid] = b_l1[tid];
    __syncthreads();
    float acc[8];
#pragma unroll
    for (int m = 0; m < 8; m++) acc[m] = 0.f;
#pragma unroll
    for (int kk = 0; kk < 64; kk++) {
        float wv = ws[kk][c];
#pragma unroll
        for (int m = 0; m < 8; m++) acc[m] += xs[r + 8 * m][kk] * wv;
    }
#pragma unroll
    for (int m = 0; m < 8; m++) {
        int gn = node0 + r + 8 * m;
        if (gn < N_NODES) {
            float v = acc[m] + bs[c];
            g_h[gn * 32 + c] = fmaxf(v, 0.f);
        }
    }
}

// ---------------- GEMM 3: ycat2 = [h@w_rel2 | h@w_root2]  [20000,32]->[20000,32]
__global__ void proj2_kernel(const float* __restrict__ w_rel,
                             const float* __restrict__ w_root) {
    __shared__ float xs[64][33];
    __shared__ float ws[32][32];
    int tid = threadIdx.x;
    int c = tid & 31;
    int r = tid >> 5;
    int node0 = blockIdx.x * 64;
    for (int t = tid; t < 64 * 32; t += 256) {
        int nn = t >> 5, kk = t & 31;
        int gn = node0 + nn;
        xs[nn][kk] = (gn < N_NODES) ? g_h[gn * 32 + kk] : 0.f;
    }
    for (int t = tid; t < 32 * 32; t += 256) {
        int kk = t >> 5, j = t & 31;
        float v = (j < 16) ? w_rel[kk * 16 + j] : w_root[kk * 16 + (j - 16)];
        ws[kk][j] = v;
    }
    __syncthreads();
    float acc[8];
#pragma unroll
    for (int m = 0; m < 8; m++) acc[m] = 0.f;
#pragma unroll
    for (int kk = 0; kk < 32; kk++) {
        float wv = ws[kk][c];
#pragma unroll
        for (int m = 0; m < 8; m++) acc[m] += xs[r + 8 * m][kk] * wv;
    }
#pragma unroll
    for (int m = 0; m < 8; m++) {
        int gn = node0 + r + 8 * m;
        if (gn < N_NODES) g_ycat2[gn * 32 + c] = acc[m];
    }
}

// ---------------- agg2: h2 = segsum(y2) + r2 + b_rel2  (half-warp per node, 16 feats)
__global__ void agg2_kernel(const float* __restrict__ b_rel) {
    int gid = blockIdx.x * blockDim.x + threadIdx.x;
    int node = gid >> 4;
    int f = gid & 15;
    if (node >= N_NODES) return;
    int beg = g_off[node], end = g_off[node + 1];
    float a = 0.f;
    int e = beg;
    for (; e + 4 <= end; e += 4) {
        int s0 = g_csr_src[e];
        int s1 = g_csr_src[e + 1];
        int s2 = g_csr_src[e + 2];
        int s3 = g_csr_src[e + 3];
        a += g_ycat2[s0 * 32 + f] + g_ycat2[s1 * 32 + f] +
             g_ycat2[s2 * 32 + f] + g_ycat2[s3 * 32 + f];
    }
    for (; e < end; e++) a += g_ycat2[g_csr_src[e] * 32 + f];
    a += g_ycat2[node * 32 + 16 + f] + b_rel[f];
    g_h2[node * 16 + f] = a;
}

// ---------------- final: out = log_softmax(h2 @ w_l2 + b_l2)  [20000,16]->[20000,10]
__global__ void final_kernel(const float* __restrict__ w_l2,
                             const float* __restrict__ b_l2,
                             float* __restrict__ out) {
    __shared__ float ws[160];
    __shared__ float bs[10];
    int tid = threadIdx.x;
    if (tid < 160) ws[tid] = w_l2[tid];
    if (tid < 10) bs[tid] = b_l2[tid];
    __syncthreads();
    int node = blockIdx.x * blockDim.x + tid;
    if (node >= N_NODES) return;
    float h[16];
#pragma unroll
    for (int k = 0; k < 16; k++) h[k] = g_h2[node * 16 + k];
    float lg[10];
#pragma unroll
    for (int j = 0; j < 10; j++) lg[j] = bs[j];
#pragma unroll
    for (int k = 0; k < 16; k++) {
        float hv = h[k];
#pragma unroll
        for (int j = 0; j < 10; j++) lg[j] += hv * ws[k * 10 + j];
    }
    float m = lg[0];
#pragma unroll
    for (int j = 1; j < 10; j++) m = fmaxf(m, lg[j]);
    float ssum = 0.f;
#pragma unroll
    for (int j = 0; j < 10; j++) ssum += expf(lg[j] - m);
    float lse = logf(ssum);
#pragma unroll
    for (int j = 0; j < 10; j++) out[node * 10 + j] = lg[j] - m - lse;
}

// ---------------- launch ----------------
extern "C" void kernel_launch(void* const* d_in, const int* in_sizes, int n_in,
                              void* d_out, int out_size) {
    const float* x       = (const float*)d_in[0];
    const void*  ei      = d_in[1];
    const float* w_rel1  = (const float*)d_in[2];
    const float* b_rel1  = (const float*)d_in[3];
    const float* w_root1 = (const float*)d_in[4];
    const float* w_l1    = (const float*)d_in[5];
    const float* b_l1    = (const float*)d_in[6];
    const float* w_rel2  = (const float*)d_in[7];
    const float* b_rel2  = (const float*)d_in[8];
    const float* w_root2 = (const float*)d_in[9];
    const float* w_l2    = (const float*)d_in[10];
    const float* b_l2    = (const float*)d_in[11];
    float* out = (float*)d_out;

    detect_kernel<<<1, 32>>>((const long long*)ei);
    zero_deg_kernel<<<(N_NODES + 255) / 256, 256>>>();
    hist_kernel<<<(N_EDGES + 255) / 256, 256>>>(ei);
    scan_kernel<<<1, 1024>>>();
    fill_kernel<<<(N_EDGES + 255) / 256, 256>>>(ei);

    proj1_kernel<<<(N_NODES + 63) / 64, 256>>>(x, w_rel1, w_root1);
    agg1_kernel<<<(N_NODES * 32 + 255) / 256, 256>>>(b_rel1);
    mlp1_kernel<<<(N_NODES + 63) / 64, 256>>>(w_l1, b_l1);
    proj2_kernel<<<(N_NODES + 63) / 64, 256>>>(w_rel2, w_root2);
    agg2_kernel<<<(N_NODES * 16 + 255) / 256, 256>>>(b_rel2);
    final_kernel<<<(N_NODES + 255) / 256, 256>>>(w_l2, b_l2, out);
}